// round 10
// baseline (speedup 1.0000x reference)
#include <cuda_runtime.h>
#include <cuda_fp16.h>
#include <cstdint>

#define BSZ  256
#define FDIM 128
#define DDIM 512
#define HH   8
#define HD   64
#define KTOP 64
#define MTOT (BSZ * FDIM)            // 32768
#define LOSCALE 2048.0f
#define INVLOSCALE (1.0f / 2048.0f)

// ---------------- scratch (device globals: allocation-free) ----------------
__device__ float g_qkv[(size_t)3 * MTOT * DDIM];   // q,k,v in (B,F,D) plain layout
__device__ float g_pv[BSZ];
__device__ __half g_xhi[(size_t)MTOT * DDIM];
__device__ __half g_xlo[(size_t)MTOT * DDIM];      // scaled by 2048
__device__ __half g_ahi[(size_t)MTOT * DDIM];      // attn out hi (written by attn_kernel)
__device__ __half g_alo[(size_t)MTOT * DDIM];      // attn out lo (scaled by 2048)
__device__ __half g_wthi[(size_t)4 * DDIM * DDIM]; // W^T (n,k) for q,k,v,o
__device__ __half g_wtlo[(size_t)4 * DDIM * DDIM]; // scaled by 2048

// ---------------- helpers ----------------
typedef unsigned long long u64c;

__device__ __forceinline__ uint32_t smem_u32(const void* p) {
    uint32_t a;
    asm("{ .reg .u64 t; cvta.to.shared.u64 t, %1; cvt.u32.u64 %0, t; }" : "=r"(a) : "l"(p));
    return a;
}
__device__ __forceinline__ void cp_async16(uint32_t dst, const void* src) {
    asm volatile("cp.async.cg.shared.global [%0], [%1], 16;" :: "r"(dst), "l"(src) : "memory");
}
__device__ __forceinline__ void cp_commit() {
    asm volatile("cp.async.commit_group;" ::: "memory");
}
template<int N>
__device__ __forceinline__ void cp_wait() {
    asm volatile("cp.async.wait_group %0;" :: "n"(N) : "memory");
}
__device__ __forceinline__ void ldm_x4(uint32_t* r, uint32_t addr) {
    asm volatile("ldmatrix.sync.aligned.m8n8.x4.shared.b16 {%0,%1,%2,%3}, [%4];"
                 : "=r"(r[0]), "=r"(r[1]), "=r"(r[2]), "=r"(r[3]) : "r"(addr));
}
__device__ __forceinline__ void mma16816(float* c, const uint32_t* a, uint32_t b0, uint32_t b1) {
    asm volatile(
        "mma.sync.aligned.m16n8k16.row.col.f32.f16.f16.f32 "
        "{%0,%1,%2,%3}, {%4,%5,%6,%7}, {%8,%9}, {%0,%1,%2,%3};"
        : "+f"(c[0]), "+f"(c[1]), "+f"(c[2]), "+f"(c[3])
        : "r"(a[0]), "r"(a[1]), "r"(a[2]), "r"(a[3]), "r"(b0), "r"(b1));
}
// packed f32x2 ops (sm_100+ base ISA)
__device__ __forceinline__ u64c pk2(float a, float b) {
    u64c r; asm("mov.b64 %0, {%1, %2};" : "=l"(r) : "f"(a), "f"(b)); return r;
}
__device__ __forceinline__ void upk2(float& a, float& b, u64c v) {
    asm("mov.b64 {%0, %1}, %2;" : "=f"(a), "=f"(b) : "l"(v));
}
__device__ __forceinline__ void fma2(u64c& d, u64c a, u64c b) {
    asm("fma.rn.f32x2 %0, %1, %2, %0;" : "+l"(d) : "l"(a), "l"(b));
}

// monotone float<->uint key mapping (larger key <=> larger float)
__device__ __forceinline__ unsigned f2k(float f) {
    unsigned u = __float_as_uint(f);
    return (u & 0x80000000u) ? ~u : (u | 0x80000000u);
}
__device__ __forceinline__ float k2f(unsigned k) {
    unsigned u = (k & 0x80000000u) ? (k ^ 0x80000000u) : ~k;
    return __uint_as_float(u);
}

// ---------------- fp16 hi/lo split of x (lo scaled by 2048) ----------------
__global__ void __launch_bounds__(256) split_kernel(const float4* __restrict__ xsrc) {
    size_t i = (size_t)blockIdx.x * 256 + threadIdx.x;   // grid sized exactly
    __half2* hi = (__half2*)g_xhi;
    __half2* lo = (__half2*)g_xlo;
    float4 v = xsrc[i];
    __half hx = __float2half(v.x), hy = __float2half(v.y);
    __half hz = __float2half(v.z), hw = __float2half(v.w);
    __half2 h0; h0.x = hx; h0.y = hy;
    __half2 h1; h1.x = hz; h1.y = hw;
    __half2 l0, l1;
    l0.x = __float2half((v.x - __half2float(hx)) * LOSCALE);
    l0.y = __float2half((v.y - __half2float(hy)) * LOSCALE);
    l1.x = __float2half((v.z - __half2float(hz)) * LOSCALE);
    l1.y = __float2half((v.w - __half2float(hw)) * LOSCALE);
    hi[2 * i] = h0; hi[2 * i + 1] = h1;
    lo[2 * i] = l0; lo[2 * i + 1] = l1;
}

// ---------------- weight transpose + split: W[k][n] -> Wt[n][k] hi/lo ----------------
__global__ void wsplit_kernel(const float* __restrict__ Wq, const float* __restrict__ Wk,
                              const float* __restrict__ Wv, const float* __restrict__ Wo) {
    int z = blockIdx.z;
    const float* W = (z == 0) ? Wq : (z == 1) ? Wk : (z == 2) ? Wv : Wo;
    __shared__ float t[32][33];
    int n0 = blockIdx.x * 32, k0 = blockIdx.y * 32;
    int tx = threadIdx.x, ty = threadIdx.y;
    t[ty][tx] = W[(size_t)(k0 + ty) * DDIM + n0 + tx];
    __syncthreads();
    float v = t[tx][ty];                      // = W[k0+tx][n0+ty]
    __half h = __float2half(v);
    size_t o = (size_t)z * DDIM * DDIM + (size_t)(n0 + ty) * DDIM + k0 + tx;
    g_wthi[o] = h;
    g_wtlo[o] = __float2half((v - __half2float(h)) * LOSCALE);
}

// ---------------- pv gating MLP: one block per batch ----------------
__global__ void __launch_bounds__(256) pv_kernel(
    const float* __restrict__ x,
    const float* __restrict__ W1, const float* __restrict__ b1,
    const float* __restrict__ W2, const float* __restrict__ b2)
{
    int b = blockIdx.x;
    int tid = threadIdx.x;
    __shared__ float comb[1024];
    __shared__ float red[256];

    for (int d = tid; d < DDIM; d += 256) {
        float s1 = 0.f, s2 = 0.f;
        const float* xb = x + (size_t)b * FDIM * DDIM;
        for (int f = 0; f < 64; f++)   s1 += xb[f * DDIM + d];
        for (int f = 64; f < 128; f++) s2 += xb[f * DDIM + d];
        comb[d]       = s1 * (1.f / 64.f);
        comb[512 + d] = s2 * (1.f / 64.f);
    }
    __syncthreads();

    float part = 0.f;
    for (int j = tid; j < DDIM; j += 256) {
        float acc = b1[j];
        for (int i = 0; i < 1024; i++) acc += comb[i] * W1[i * DDIM + j];
        float hsil = acc / (1.f + __expf(-acc));
        part += hsil * W2[j];
    }
    red[tid] = part;
    for (int s = 128; s > 0; s >>= 1) {
        __syncthreads();
        if (tid < s) red[tid] += red[tid + s];
    }
    __syncthreads();
    if (tid == 0) {
        float z = red[0] + b2[0];
        g_pv[b] = 1.f / (1.f + __expf(-z));
    }
}

// ---------------- HMMA fp16 3-term split GEMM: C[M,512] = A[M,512] @ W + bias ----------------
#define KC      64
#define ROWH    72
#define NCHUNK  24
#define NSTAGE  3
#define TILE_HALF (128 * ROWH)                        // 9216 halves = 18432 B
#define GEMM_SMEM (NSTAGE * TILE_HALF * 2 * 2)        // 110592 bytes

__global__ void __launch_bounds__(256, 2) gemm_mma(
    int mode,
    const float* __restrict__ b0, const float* __restrict__ b1, const float* __restrict__ b2,
    float* __restrict__ Cout)
{
    extern __shared__ __half gsm[];
    uint32_t sAu = smem_u32(gsm);
    uint32_t sBu = smem_u32(gsm + NSTAGE * TILE_HALF);

    int tid  = threadIdx.x;
    int lane = tid & 31;
    int wid  = tid >> 5;
    int wm   = wid & 3;          // 0..3 -> M offset 32*wm
    int wn   = wid >> 2;         // 0..1 -> N offset 64*wn
    int z    = blockIdx.z;

    const __half* Ahi = mode ? g_ahi : g_xhi;
    const __half* Alo = mode ? g_alo : g_xlo;
    int wz = mode ? 3 : z;
    const __half* Bhi = g_wthi + (size_t)wz * DDIM * DDIM;
    const __half* Blo = g_wtlo + (size_t)wz * DDIM * DDIM;
    const float* bias = (z == 0) ? b0 : (z == 1) ? b1 : b2;
    float* C = mode ? Cout : (g_qkv + (size_t)z * MTOT * DDIM);

    int bm = blockIdx.y * 128;
    int bn = blockIdx.x * 128;

    float acc[2][8][4];
#pragma unroll
    for (int mi = 0; mi < 2; mi++)
#pragma unroll
        for (int nj = 0; nj < 8; nj++)
#pragma unroll
            for (int q = 0; q < 4; q++) acc[mi][nj][q] = 0.f;

    auto issue = [&](int cc, int buf) {
        int p  = cc >> 3;                      // 0: hi*lo', 1: lo'*hi, 2: hi*hi
        int k0 = (cc & 7) * KC;
        const __half* As = (p == 1) ? Alo : Ahi;
        const __half* Bs = (p == 0) ? Blo : Bhi;
        uint32_t base = (uint32_t)buf * TILE_HALF * 2;
#pragma unroll
        for (int rep = 0; rep < 4; rep++) {
            int idx = rep * 256 + tid;
            int row = idx >> 3, seg = idx & 7;
            uint32_t so = base + (uint32_t)(row * ROWH + seg * 8) * 2;
            cp_async16(sAu + so, As + (size_t)(bm + row) * DDIM + k0 + seg * 8);
            cp_async16(sBu + so, Bs + (size_t)(bn + row) * DDIM + k0 + seg * 8);
        }
        cp_commit();
    };

    issue(0, 0);
    issue(1, 1);
    int cbuf = 0, nbuf = 2;
    for (int cc = 0; cc < NCHUNK; ++cc) {
        cp_wait<1>();
        __syncthreads();
        if (cc + 2 < NCHUNK) issue(cc + 2, nbuf);
        else                 cp_commit();          // keep group count uniform

        uint32_t base = (uint32_t)cbuf * TILE_HALF * 2;
        uint32_t aB = sAu + base, bB = sBu + base;
#pragma unroll
        for (int kk4 = 0; kk4 < 4; kk4++) {      // four k16 groups of the 64-chunk
            uint32_t afr[2][4], bfr[4][4];
            uint32_t colb = (uint32_t)(kk4 * 16 + (lane >> 4) * 8) * 2;
#pragma unroll
            for (int mi = 0; mi < 2; mi++) {
                uint32_t addr = aB + (uint32_t)((wm * 32 + mi * 16 + (lane & 15)) * ROWH) * 2 + colb;
                ldm_x4(afr[mi], addr);
            }
#pragma unroll
            for (int ni = 0; ni < 4; ni++) {
                uint32_t addr = bB + (uint32_t)((wn * 64 + ni * 16 + (lane & 15)) * ROWH) * 2 + colb;
                ldm_x4(bfr[ni], addr);
            }
#pragma unroll
            for (int mi = 0; mi < 2; mi++)
#pragma unroll
                for (int nj = 0; nj < 8; nj++) {
                    int ni = nj >> 1, h2 = nj & 1;
                    mma16816(acc[mi][nj], afr[mi], bfr[ni][h2], bfr[ni][h2 + 2]);
                }
        }
        if (cc == 15) {
#pragma unroll
            for (int mi = 0; mi < 2; mi++)
#pragma unroll
                for (int nj = 0; nj < 8; nj++)
#pragma unroll
                    for (int q = 0; q < 4; q++) acc[mi][nj][q] *= INVLOSCALE;
        }
        cbuf = (cbuf + 1 == NSTAGE) ? 0 : cbuf + 1;
        nbuf = (nbuf + 1 == NSTAGE) ? 0 : nbuf + 1;
    }

    int rbase = bm + wm * 32 + (lane >> 2);
    int cb    = bn + wn * 64 + 2 * (lane & 3);
#pragma unroll
    for (int mi = 0; mi < 2; mi++) {
#pragma unroll
        for (int nj = 0; nj < 8; nj++) {
            int col = cb + nj * 8;
            float bx = bias[col], by = bias[col + 1];
            float2 v0 = make_float2(acc[mi][nj][0] + bx, acc[mi][nj][1] + by);
            float2 v1 = make_float2(acc[mi][nj][2] + bx, acc[mi][nj][3] + by);
            int r0 = rbase + mi * 16;
            *(float2*)(C + (size_t)r0 * DDIM + col)       = v0;
            *(float2*)(C + (size_t)(r0 + 8) * DDIM + col) = v1;
        }
    }
}

// ---------------- fused attention: one CTA per (b,h), 2 threads per row ----------------
// Pair (lane 2r, 2r+1) splits the j-range; combine via shfl_xor(1).
// Row stride 132 words (16B-aligned rows, conflict-light LDS.128).
#define SROWW 132
#define SMEM_ATTN ((128 * SROWW + 128 * 64) * 4)   // 100352 bytes

__global__ void __launch_bounds__(256, 2) attn_kernel(
    const float* __restrict__ corr,
    const float* __restrict__ fimp)
{
    extern __shared__ float sm[];
    unsigned* scu = (unsigned*)sm;            // 128 rows x 132 words of keys
    float*    kv  = sm + 128 * SROWW;         // 128*64 (k tile, then v tile)

    int bh = blockIdx.x;
    int b = bh >> 3, hh = bh & 7;
    int tid = threadIdx.x;
    int r  = tid >> 1;                        // row 0..127
    int hf = tid & 1;                         // half 0/1
    int j0 = hf << 6;                         // own j range start

    const float* qbase = g_qkv + (size_t)b * FDIM * DDIM + hh * HD;
    const float* kbase = qbase + (size_t)MTOT * DDIM;
    const float* vbase = qbase + (size_t)2 * MTOT * DDIM;

    // K tile (coalesced)
    for (int i = tid; i < 2048; i += 256) {
        int row = i >> 4, seg = i & 15;
        *(float4*)(kv + row * 64 + seg * 4) =
            *(const float4*)(kbase + (size_t)row * DDIM + seg * 4);
    }
    // full q row packed into f32x2 registers (both pair threads load it)
    u64c qv2[32];
    const float4* qp = (const float4*)(qbase + (size_t)r * DDIM);
#pragma unroll
    for (int d = 0; d < 16; d++) {
        float4 t = qp[d];
        qv2[2 * d]     = pk2(t.x, t.y);
        qv2[2 * d + 1] = pk2(t.z, t.w);
    }
    __syncthreads();

    float fi_r = fimp[r];
    float pvh  = g_pv[b] * 0.5f;
    bool  rlo  = (r < 64);
    const float* crow = corr + r * FDIM;
    unsigned* srow = scu + r * SROWW;

    // scores for own 64 j's; STS.128 every 4; inline row-max
    unsigned kmax = 0u;
    for (int g = 0; g < 16; g++) {
        unsigned k4[4];
#pragma unroll
        for (int t = 0; t < 4; t++) {
            int j = j0 + g * 4 + t;
            const ulonglong2* kp = (const ulonglong2*)(kv + j * HD);
            u64c c0 = 0, c1 = 0, c2 = 0, c3 = 0;
#pragma unroll
            for (int d = 0; d < 16; d += 2) {
                ulonglong2 t0 = kp[d], t1 = kp[d + 1];
                fma2(c0, qv2[2 * d],     t0.x);
                fma2(c1, qv2[2 * d + 1], t0.y);
                fma2(c2, qv2[2 * d + 2], t1.x);
                fma2(c3, qv2[2 * d + 3], t1.y);
            }
            float x0, x1, y0, y1, z0, z1, w0, w1;
            upk2(x0, x1, c0); upk2(y0, y1, c1); upk2(z0, z1, c2); upk2(w0, w1, c3);
            float s = (((x0 + x1) + (y0 + y1)) + ((z0 + z1) + (w0 + w1))) * 0.125f
                    + crow[j] * fi_r * fimp[j];
            if (rlo != (j < 64)) s += pvh;
            unsigned key = f2k(s);
            kmax = max(kmax, key);
            k4[t] = key;
        }
        *(uint4*)(srow + j0 + g * 4) = make_uint4(k4[0], k4[1], k4[2], k4[3]);
    }
    kmax = max(kmax, __shfl_xor_sync(0xffffffffu, kmax, 1));   // pair row-max
    __syncthreads();   // everyone done reading K / writing keys

    // overwrite kv with V tile
    for (int i = tid; i < 2048; i += 256) {
        int row = i >> 4, seg = i & 15;
        *(float4*)(kv + row * 64 + seg * 4) =
            *(const float4*)(vbase + (size_t)row * DDIM + seg * 4);
    }

    // exact 64th-largest via 1-bit radix; each pair thread counts its 64 keys (uint4 loads)
    const uint4* s4 = (const uint4*)(srow + j0);
    unsigned prefix = 0u;
    int kk = KTOP;
    for (int bit = 31; bit >= 0; --bit) {
        unsigned want = (prefix >> bit) | 1u;
        int c = 0;
#pragma unroll 4
        for (int g = 0; g < 16; g++) {
            uint4 kq = s4[g];
            c += (int)((kq.x >> bit) == want);
            c += (int)((kq.y >> bit) == want);
            c += (int)((kq.z >> bit) == want);
            c += (int)((kq.w >> bit) == want);
        }
        c += __shfl_xor_sync(0xffffffffu, c, 1);
        if (c >= kk) prefix |= (1u << bit); else kk -= c;
    }
    float m = k2f(kmax);

    __syncthreads();   // V tile fully loaded

    // exp + sum + AV accumulate over own 64 j's (full 64-dim accumulators)
    u64c av[32];
#pragma unroll
    for (int d = 0; d < 32; d++) av[d] = 0ull;
    float ssum = 0.f;
    for (int g = 0; g < 16; g++) {
        uint4 kq = s4[g];
        unsigned keys[4] = { kq.x, kq.y, kq.z, kq.w };
#pragma unroll
        for (int t = 0; t < 4; t++) {
            unsigned key = keys[t];
            float e = (key >= prefix) ? __expf(k2f(key) - m) : 0.f;
            ssum += e;
            u64c e2 = pk2(e, e);
            const ulonglong2* vp = (const ulonglong2*)(kv + (j0 + g * 4 + t) * HD);
#pragma unroll
            for (int d = 0; d < 16; d++) {
                ulonglong2 tv = vp[d];
                fma2(av[2 * d],     e2, tv.x);
                fma2(av[2 * d + 1], e2, tv.y);
            }
        }
    }
    ssum += __shfl_xor_sync(0xffffffffu, ssum, 1);   // pair-combined denominator
    float inv = 1.f / ssum;

    // pair-combine AV and write own half (dims [32*hf, 32*hf+32)) as fp16 hi/lo
    size_t orow = ((size_t)b * FDIM + r) * DDIM + hh * HD;
    __half2* hi2 = (__half2*)(g_ahi + orow);
    __half2* lo2 = (__half2*)(g_alo + orow);
#pragma unroll
    for (int d = 0; d < 32; d++) {
        u64c oth = __shfl_xor_sync(0xffffffffu, av[d], 1);
        if ((d >> 4) == hf) {
            float a, bb, oa, ob;
            upk2(a, bb, av[d]);
            upk2(oa, ob, oth);
            a = (a + oa) * inv; bb = (bb + ob) * inv;
            __half ha = __float2half(a), hb = __float2half(bb);
            hi2[d] = __halves2half2(ha, hb);
            lo2[d] = __halves2half2(__float2half((a  - __half2float(ha)) * LOSCALE),
                                    __float2half((bb - __half2float(hb)) * LOSCALE));
        }
    }
}

// ---------------- launch ----------------
extern "C" void kernel_launch(void* const* d_in, const int* in_sizes, int n_in,
                              void* d_out, int out_size)
{
    const float* x    = (const float*)d_in[0];
    const float* Wq   = (const float*)d_in[1];
    const float* bq   = (const float*)d_in[2];
    const float* Wk   = (const float*)d_in[3];
    const float* bk   = (const float*)d_in[4];
    const float* Wv   = (const float*)d_in[5];
    const float* bv   = (const float*)d_in[6];
    const float* Wo   = (const float*)d_in[7];
    const float* bo   = (const float*)d_in[8];
    const float* corr = (const float*)d_in[9];
    const float* fimp = (const float*)d_in[10];
    const float* W1   = (const float*)d_in[11];
    const float* b1   = (const float*)d_in[12];
    const float* W2   = (const float*)d_in[13];
    const float* b2   = (const float*)d_in[14];
    float* out = (float*)d_out;

    cudaFuncSetAttribute(gemm_mma, cudaFuncAttributeMaxDynamicSharedMemorySize, GEMM_SMEM);
    cudaFuncSetAttribute(attn_kernel, cudaFuncAttributeMaxDynamicSharedMemorySize, SMEM_ATTN);

    // prep: fp16 hi/lo splits of x and transposed weights
    split_kernel<<<16384, 256>>>((const float4*)x);
    wsplit_kernel<<<dim3(16, 16, 4), dim3(32, 32)>>>(Wq, Wk, Wv, Wo);
    pv_kernel<<<BSZ, 256>>>(x, W1, b1, W2, b2);

    // q,k,v projections on tensor cores (HMMA, 3-term split, K64 chunks)
    gemm_mma<<<dim3(4, 256, 3), 256, GEMM_SMEM>>>(0, bq, bk, bv, nullptr);

    // fused sparse attention (2 threads/row; writes hi/lo split output directly)
    attn_kernel<<<BSZ * HH, 256, SMEM_ATTN>>>(corr, fimp);

    // output projection on tensor cores
    gemm_mma<<<dim3(4, 256, 1), 256, GEMM_SMEM>>>(1, bo, bo, bo, out);
}

// round 11
// speedup vs baseline: 1.4947x; 1.4947x over previous
#include <cuda_runtime.h>
#include <cuda_fp16.h>
#include <cstdint>

#define BSZ  256
#define FDIM 128
#define DDIM 512
#define HH   8
#define HD   64
#define KTOP 64
#define MTOT (BSZ * FDIM)            // 32768
#define LOSCALE 2048.0f
#define INVLOSCALE (1.0f / 2048.0f)

// ---------------- scratch (device globals: allocation-free) ----------------
__device__ float g_qkv[(size_t)3 * MTOT * DDIM];   // q,k,v in (B,F,D) plain layout
__device__ float g_pv[BSZ];
__device__ __half g_xhi[(size_t)MTOT * DDIM];
__device__ __half g_xlo[(size_t)MTOT * DDIM];      // scaled by 2048
__device__ __half g_ahi[(size_t)MTOT * DDIM];      // attn out hi (written by attn_kernel)
__device__ __half g_alo[(size_t)MTOT * DDIM];      // attn out lo (scaled by 2048)
__device__ __half g_wthi[(size_t)4 * DDIM * DDIM]; // W^T (n,k) for q,k,v,o
__device__ __half g_wtlo[(size_t)4 * DDIM * DDIM]; // scaled by 2048

// ---------------- helpers ----------------
typedef unsigned long long u64c;

__device__ __forceinline__ uint32_t smem_u32(const void* p) {
    uint32_t a;
    asm("{ .reg .u64 t; cvta.to.shared.u64 t, %1; cvt.u32.u64 %0, t; }" : "=r"(a) : "l"(p));
    return a;
}
__device__ __forceinline__ void cp_async16(uint32_t dst, const void* src) {
    asm volatile("cp.async.cg.shared.global [%0], [%1], 16;" :: "r"(dst), "l"(src) : "memory");
}
__device__ __forceinline__ void cp_commit() {
    asm volatile("cp.async.commit_group;" ::: "memory");
}
template<int N>
__device__ __forceinline__ void cp_wait() {
    asm volatile("cp.async.wait_group %0;" :: "n"(N) : "memory");
}
__device__ __forceinline__ void ldm_x4(uint32_t* r, uint32_t addr) {
    asm volatile("ldmatrix.sync.aligned.m8n8.x4.shared.b16 {%0,%1,%2,%3}, [%4];"
                 : "=r"(r[0]), "=r"(r[1]), "=r"(r[2]), "=r"(r[3]) : "r"(addr));
}
__device__ __forceinline__ void mma16816(float* c, const uint32_t* a, uint32_t b0, uint32_t b1) {
    asm volatile(
        "mma.sync.aligned.m16n8k16.row.col.f32.f16.f16.f32 "
        "{%0,%1,%2,%3}, {%4,%5,%6,%7}, {%8,%9}, {%0,%1,%2,%3};"
        : "+f"(c[0]), "+f"(c[1]), "+f"(c[2]), "+f"(c[3])
        : "r"(a[0]), "r"(a[1]), "r"(a[2]), "r"(a[3]), "r"(b0), "r"(b1));
}
// monotone float<->uint key mapping (larger key <=> larger float)
__device__ __forceinline__ unsigned f2k(float f) {
    unsigned u = __float_as_uint(f);
    return (u & 0x80000000u) ? ~u : (u | 0x80000000u);
}
__device__ __forceinline__ float k2f(unsigned k) {
    unsigned u = (k & 0x80000000u) ? (k ^ 0x80000000u) : ~k;
    return __uint_as_float(u);
}
__device__ __forceinline__ uint32_t h2pack(float a, float b) {
    __half2 h = __floats2half2_rn(a, b);
    return *(uint32_t*)&h;
}
// split (a,b) into packed fp16 hi and scaled-lo
__device__ __forceinline__ void split2(float a, float b, uint32_t& hi, uint32_t& lo) {
    __half ha = __float2half(a), hb = __float2half(b);
    __half2 hh = __halves2half2(ha, hb);
    hi = *(uint32_t*)&hh;
    lo = h2pack((a - __half2float(ha)) * LOSCALE, (b - __half2float(hb)) * LOSCALE);
}

// ---------------- fp16 hi/lo split of x (lo scaled by 2048) ----------------
__global__ void __launch_bounds__(256) split_kernel(const float4* __restrict__ xsrc) {
    size_t i = (size_t)blockIdx.x * 256 + threadIdx.x;   // grid sized exactly
    __half2* hi = (__half2*)g_xhi;
    __half2* lo = (__half2*)g_xlo;
    float4 v = xsrc[i];
    uint32_t h0, l0, h1, l1;
    split2(v.x, v.y, h0, l0);
    split2(v.z, v.w, h1, l1);
    hi[2 * i] = *(__half2*)&h0; hi[2 * i + 1] = *(__half2*)&h1;
    lo[2 * i] = *(__half2*)&l0; lo[2 * i + 1] = *(__half2*)&l1;
}

// ---------------- weight transpose + split: W[k][n] -> Wt[n][k] hi/lo ----------------
__global__ void wsplit_kernel(const float* __restrict__ Wq, const float* __restrict__ Wk,
                              const float* __restrict__ Wv, const float* __restrict__ Wo) {
    int z = blockIdx.z;
    const float* W = (z == 0) ? Wq : (z == 1) ? Wk : (z == 2) ? Wv : Wo;
    __shared__ float t[32][33];
    int n0 = blockIdx.x * 32, k0 = blockIdx.y * 32;
    int tx = threadIdx.x, ty = threadIdx.y;
    t[ty][tx] = W[(size_t)(k0 + ty) * DDIM + n0 + tx];
    __syncthreads();
    float v = t[tx][ty];                      // = W[k0+tx][n0+ty]
    __half h = __float2half(v);
    size_t o = (size_t)z * DDIM * DDIM + (size_t)(n0 + ty) * DDIM + k0 + tx;
    g_wthi[o] = h;
    g_wtlo[o] = __float2half((v - __half2float(h)) * LOSCALE);
}

// ---------------- pv gating MLP: one block per batch ----------------
__global__ void __launch_bounds__(256) pv_kernel(
    const float* __restrict__ x,
    const float* __restrict__ W1, const float* __restrict__ b1,
    const float* __restrict__ W2, const float* __restrict__ b2)
{
    int b = blockIdx.x;
    int tid = threadIdx.x;
    __shared__ float comb[1024];
    __shared__ float red[256];

    for (int d = tid; d < DDIM; d += 256) {
        float s1 = 0.f, s2 = 0.f;
        const float* xb = x + (size_t)b * FDIM * DDIM;
        for (int f = 0; f < 64; f++)   s1 += xb[f * DDIM + d];
        for (int f = 64; f < 128; f++) s2 += xb[f * DDIM + d];
        comb[d]       = s1 * (1.f / 64.f);
        comb[512 + d] = s2 * (1.f / 64.f);
    }
    __syncthreads();

    float part = 0.f;
    for (int j = tid; j < DDIM; j += 256) {
        float acc = b1[j];
        for (int i = 0; i < 1024; i++) acc += comb[i] * W1[i * DDIM + j];
        float hsil = acc / (1.f + __expf(-acc));
        part += hsil * W2[j];
    }
    red[tid] = part;
    for (int s = 128; s > 0; s >>= 1) {
        __syncthreads();
        if (tid < s) red[tid] += red[tid + s];
    }
    __syncthreads();
    if (tid == 0) {
        float z = red[0] + b2[0];
        g_pv[b] = 1.f / (1.f + __expf(-z));
    }
}

// ---------------- HMMA fp16 3-term split GEMM: C[M,512] = A[M,512] @ W + bias ----------------
#define KC      64
#define ROWH    72
#define NCHUNK  24
#define NSTAGE  3
#define TILE_HALF (128 * ROWH)                        // 9216 halves = 18432 B
#define GEMM_SMEM (NSTAGE * TILE_HALF * 2 * 2)        // 110592 bytes

__global__ void __launch_bounds__(256, 2) gemm_mma(
    int mode,
    const float* __restrict__ b0, const float* __restrict__ b1, const float* __restrict__ b2,
    float* __restrict__ Cout)
{
    extern __shared__ __half gsm[];
    uint32_t sAu = smem_u32(gsm);
    uint32_t sBu = smem_u32(gsm + NSTAGE * TILE_HALF);

    int tid  = threadIdx.x;
    int lane = tid & 31;
    int wid  = tid >> 5;
    int wm   = wid & 3;
    int wn   = wid >> 2;
    int z    = blockIdx.z;

    const __half* Ahi = mode ? g_ahi : g_xhi;
    const __half* Alo = mode ? g_alo : g_xlo;
    int wz = mode ? 3 : z;
    const __half* Bhi = g_wthi + (size_t)wz * DDIM * DDIM;
    const __half* Blo = g_wtlo + (size_t)wz * DDIM * DDIM;
    const float* bias = (z == 0) ? b0 : (z == 1) ? b1 : b2;
    float* C = mode ? Cout : (g_qkv + (size_t)z * MTOT * DDIM);

    int bm = blockIdx.y * 128;
    int bn = blockIdx.x * 128;

    float acc[2][8][4];
#pragma unroll
    for (int mi = 0; mi < 2; mi++)
#pragma unroll
        for (int nj = 0; nj < 8; nj++)
#pragma unroll
            for (int q = 0; q < 4; q++) acc[mi][nj][q] = 0.f;

    auto issue = [&](int cc, int buf) {
        int p  = cc >> 3;
        int k0 = (cc & 7) * KC;
        const __half* As = (p == 1) ? Alo : Ahi;
        const __half* Bs = (p == 0) ? Blo : Bhi;
        uint32_t base = (uint32_t)buf * TILE_HALF * 2;
#pragma unroll
        for (int rep = 0; rep < 4; rep++) {
            int idx = rep * 256 + tid;
            int row = idx >> 3, seg = idx & 7;
            uint32_t so = base + (uint32_t)(row * ROWH + seg * 8) * 2;
            cp_async16(sAu + so, As + (size_t)(bm + row) * DDIM + k0 + seg * 8);
            cp_async16(sBu + so, Bs + (size_t)(bn + row) * DDIM + k0 + seg * 8);
        }
        cp_commit();
    };

    issue(0, 0);
    issue(1, 1);
    int cbuf = 0, nbuf = 2;
    for (int cc = 0; cc < NCHUNK; ++cc) {
        cp_wait<1>();
        __syncthreads();
        if (cc + 2 < NCHUNK) issue(cc + 2, nbuf);
        else                 cp_commit();

        uint32_t base = (uint32_t)cbuf * TILE_HALF * 2;
        uint32_t aB = sAu + base, bB = sBu + base;
#pragma unroll
        for (int kk4 = 0; kk4 < 4; kk4++) {
            uint32_t afr[2][4], bfr[4][4];
            uint32_t colb = (uint32_t)(kk4 * 16 + (lane >> 4) * 8) * 2;
#pragma unroll
            for (int mi = 0; mi < 2; mi++) {
                uint32_t addr = aB + (uint32_t)((wm * 32 + mi * 16 + (lane & 15)) * ROWH) * 2 + colb;
                ldm_x4(afr[mi], addr);
            }
#pragma unroll
            for (int ni = 0; ni < 4; ni++) {
                uint32_t addr = bB + (uint32_t)((wn * 64 + ni * 16 + (lane & 15)) * ROWH) * 2 + colb;
                ldm_x4(bfr[ni], addr);
            }
#pragma unroll
            for (int mi = 0; mi < 2; mi++)
#pragma unroll
                for (int nj = 0; nj < 8; nj++) {
                    int ni = nj >> 1, h2 = nj & 1;
                    mma16816(acc[mi][nj], afr[mi], bfr[ni][h2], bfr[ni][h2 + 2]);
                }
        }
        if (cc == 15) {
#pragma unroll
            for (int mi = 0; mi < 2; mi++)
#pragma unroll
                for (int nj = 0; nj < 8; nj++)
#pragma unroll
                    for (int q = 0; q < 4; q++) acc[mi][nj][q] *= INVLOSCALE;
        }
        cbuf = (cbuf + 1 == NSTAGE) ? 0 : cbuf + 1;
        nbuf = (nbuf + 1 == NSTAGE) ? 0 : nbuf + 1;
    }

    int rbase = bm + wm * 32 + (lane >> 2);
    int cb    = bn + wn * 64 + 2 * (lane & 3);
#pragma unroll
    for (int mi = 0; mi < 2; mi++) {
#pragma unroll
        for (int nj = 0; nj < 8; nj++) {
            int col = cb + nj * 8;
            float bx = bias[col], by = bias[col + 1];
            float2 v0 = make_float2(acc[mi][nj][0] + bx, acc[mi][nj][1] + by);
            float2 v1 = make_float2(acc[mi][nj][2] + bx, acc[mi][nj][3] + by);
            int r0 = rbase + mi * 16;
            *(float2*)(C + (size_t)r0 * DDIM + col)       = v0;
            *(float2*)(C + (size_t)(r0 + 8) * DDIM + col) = v1;
        }
    }
}

// ---------------- fused attention on tensor cores: one CTA per (b,h) ----------------
// QK^T and P.V via mma.sync with 3-term fp16 hi/lo splits; radix select fully
// in registers (fragment-space, quad shuffles). One __syncthreads total.
#define AQK 72    // halves per row, Q/K tiles (144B rows)
#define AVT 136   // halves per row, V^T tiles (272B rows)
#define OFF_QHI  0
#define OFF_QLO  18432
#define OFF_KHI  36864
#define OFF_KLO  55296
#define OFF_VTHI 73728
#define OFF_VTLO 91136
#define OFF_FIMP 108544
#define ATTN_SMEM 109056

__global__ void __launch_bounds__(256, 2) attn_kernel(
    const float* __restrict__ corr,
    const float* __restrict__ fimp)
{
    extern __shared__ __align__(16) char smem[];
    __half* sQhi = (__half*)(smem + OFF_QHI);
    __half* sQlo = (__half*)(smem + OFF_QLO);
    __half* sKhi = (__half*)(smem + OFF_KHI);
    __half* sKlo = (__half*)(smem + OFF_KLO);
    __half* sVhi = (__half*)(smem + OFF_VTHI);
    __half* sVlo = (__half*)(smem + OFF_VTLO);
    float*  sfi  = (float*)(smem + OFF_FIMP);

    int tid  = threadIdx.x;
    int lane = tid & 31;
    int warp = tid >> 5;
    int bh = blockIdx.x;
    int b = bh >> 3, h = bh & 7;

    const float* qb = g_qkv + (size_t)b * FDIM * DDIM + h * HD;
    const float* kb = qb + (size_t)MTOT * DDIM;
    const float* vb = qb + (size_t)2 * MTOT * DDIM;

    // ---- stage Q, K (row-major, 72-half stride) and V^T (d-major, 136-half stride) ----
    {
        int f  = tid >> 1;
        int d0 = (tid & 1) * 32;
#pragma unroll
        for (int i = 0; i < 8; i++) {
            int d = d0 + 4 * i;
            float4 v = *(const float4*)(qb + (size_t)f * DDIM + d);
            uint32_t h0, l0, h1, l1;
            split2(v.x, v.y, h0, l0);
            split2(v.z, v.w, h1, l1);
            *(uint32_t*)(sQhi + f * AQK + d)     = h0;
            *(uint32_t*)(sQhi + f * AQK + d + 2) = h1;
            *(uint32_t*)(sQlo + f * AQK + d)     = l0;
            *(uint32_t*)(sQlo + f * AQK + d + 2) = l1;
        }
#pragma unroll
        for (int i = 0; i < 8; i++) {
            int d = d0 + 4 * i;
            float4 v = *(const float4*)(kb + (size_t)f * DDIM + d);
            uint32_t h0, l0, h1, l1;
            split2(v.x, v.y, h0, l0);
            split2(v.z, v.w, h1, l1);
            *(uint32_t*)(sKhi + f * AQK + d)     = h0;
            *(uint32_t*)(sKhi + f * AQK + d + 2) = h1;
            *(uint32_t*)(sKlo + f * AQK + d)     = l0;
            *(uint32_t*)(sKlo + f * AQK + d + 2) = l1;
        }
        int j = f;   // V row index
#pragma unroll
        for (int i = 0; i < 8; i++) {
            int d = d0 + 4 * i;
            float4 v = *(const float4*)(vb + (size_t)j * DDIM + d);
            float vals[4] = { v.x, v.y, v.z, v.w };
#pragma unroll
            for (int c = 0; c < 4; c++) {
                __half hv = __float2half(vals[c]);
                sVhi[(d + c) * AVT + j] = hv;
                sVlo[(d + c) * AVT + j] = __float2half((vals[c] - __half2float(hv)) * LOSCALE);
            }
        }
        if (tid < FDIM) sfi[tid] = fimp[tid];
    }
    __syncthreads();   // the only block-wide sync

    uint32_t uQhi = smem_u32(sQhi), uQlo = smem_u32(sQlo);
    uint32_t uKhi = smem_u32(sKhi), uKlo = smem_u32(sKlo);
    uint32_t uVhi = smem_u32(sVhi), uVlo = smem_u32(sVlo);

    // ---- scores: S = Q.K^T via 3-term split mma ----
    float acc[16][4];
#pragma unroll
    for (int t = 0; t < 16; t++)
#pragma unroll
        for (int q = 0; q < 4; q++) acc[t][q] = 0.f;

    uint32_t arow = (uint32_t)(warp * 16 + (lane & 15)) * AQK * 2;
    uint32_t acol = (uint32_t)((lane >> 4) * 8) * 2;

#pragma unroll
    for (int p = 0; p < 3; p++) {                 // 0: Qhi*Klo', 1: Qlo'*Khi, 2: Qhi*Khi
        uint32_t aB = (p == 1) ? uQlo : uQhi;
        uint32_t bB = (p == 0) ? uKlo : uKhi;
#pragma unroll 1
        for (int ks = 0; ks < 4; ks++) {
            uint32_t colb = (uint32_t)(ks * 16) * 2 + acol;
            uint32_t afr[4];
            ldm_x4(afr, aB + arow + colb);
#pragma unroll
            for (int g = 0; g < 8; g++) {
                uint32_t bfr[4];
                ldm_x4(bfr, bB + (uint32_t)(g * 16 + (lane & 15)) * AQK * 2 + colb);
                mma16816(acc[2 * g],     afr, bfr[0], bfr[2]);
                mma16816(acc[2 * g + 1], afr, bfr[1], bfr[3]);
            }
        }
        if (p == 1) {
#pragma unroll
            for (int t = 0; t < 16; t++)
#pragma unroll
                for (int q = 0; q < 4; q++) acc[t][q] *= INVLOSCALE;
        }
    }

    // ---- bias terms + key conversion (fragment-space) ----
    int r0 = warp * 16 + (lane >> 2);
    int r1 = r0 + 8;
    float fr0 = sfi[r0], fr1 = sfi[r1];
    float pvh = g_pv[b] * 0.5f;
    bool  rl0 = (r0 < 64), rl1 = (r1 < 64);

    unsigned k0[32], k1[32];
    unsigned km0 = 0, km1 = 0;
#pragma unroll
    for (int t = 0; t < 16; t++) {
        int j0 = t * 8 + 2 * (lane & 3);
        float2 c0 = *(const float2*)(corr + r0 * FDIM + j0);
        float2 c1 = *(const float2*)(corr + r1 * FDIM + j0);
        float fj0 = sfi[j0], fj1 = sfi[j0 + 1];
        bool jl = (j0 < 64);                    // j0,j0+1 same side (j0 even, != 63)
        float m0 = (rl0 != jl) ? pvh : 0.f;
        float m1 = (rl1 != jl) ? pvh : 0.f;
        float s;
        s = acc[t][0] * 0.125f + c0.x * fr0 * fj0 + m0; k0[2 * t] = f2k(s);     km0 = max(km0, k0[2 * t]);
        s = acc[t][1] * 0.125f + c0.y * fr0 * fj1 + m0; k0[2 * t + 1] = f2k(s); km0 = max(km0, k0[2 * t + 1]);
        s = acc[t][2] * 0.125f + c1.x * fr1 * fj0 + m1; k1[2 * t] = f2k(s);     km1 = max(km1, k1[2 * t]);
        s = acc[t][3] * 0.125f + c1.y * fr1 * fj1 + m1; k1[2 * t + 1] = f2k(s); km1 = max(km1, k1[2 * t + 1]);
    }
    km0 = max(km0, __shfl_xor_sync(0xffffffffu, km0, 1));
    km0 = max(km0, __shfl_xor_sync(0xffffffffu, km0, 2));
    km1 = max(km1, __shfl_xor_sync(0xffffffffu, km1, 1));
    km1 = max(km1, __shfl_xor_sync(0xffffffffu, km1, 2));

    // ---- exact 64th-largest per row: register radix + quad-combined counts ----
    unsigned p0 = 0, p1 = 0;
    int kk0 = KTOP, kk1 = KTOP;
    for (int bit = 31; bit >= 0; --bit) {
        unsigned w0 = (p0 >> bit) | 1u, w1 = (p1 >> bit) | 1u;
        int c0 = 0, c1 = 0;
#pragma unroll
        for (int i = 0; i < 32; i++) {
            c0 += (int)((k0[i] >> bit) == w0);
            c1 += (int)((k1[i] >> bit) == w1);
        }
        int cp = c0 | (c1 << 16);
        cp += __shfl_xor_sync(0xffffffffu, cp, 1);
        cp += __shfl_xor_sync(0xffffffffu, cp, 2);
        c0 = cp & 0xffff; c1 = cp >> 16;
        if (c0 >= kk0) p0 |= 1u << bit; else kk0 -= c0;
        if (c1 >= kk1) p1 |= 1u << bit; else kk1 -= c1;
    }

    // ---- exp (in place) + row sums ----
    float m0f = k2f(km0), m1f = k2f(km1);
    float ss0 = 0.f, ss1 = 0.f;
#pragma unroll
    for (int i = 0; i < 32; i++) {
        unsigned ky = k0[i];
        float e = (ky >= p0) ? __expf(k2f(ky) - m0f) : 0.f;
        ss0 += e; k0[i] = __float_as_uint(e);
        ky = k1[i];
        e = (ky >= p1) ? __expf(k2f(ky) - m1f) : 0.f;
        ss1 += e; k1[i] = __float_as_uint(e);
    }
    ss0 += __shfl_xor_sync(0xffffffffu, ss0, 1);
    ss0 += __shfl_xor_sync(0xffffffffu, ss0, 2);
    ss1 += __shfl_xor_sync(0xffffffffu, ss1, 1);
    ss1 += __shfl_xor_sync(0xffffffffu, ss1, 2);
    float inv0 = 1.f / ss0, inv1 = 1.f / ss1;

    // ---- AV = P.V via 3-term split mma (P packed from fragments) ----
    float av[8][4];
#pragma unroll
    for (int t = 0; t < 8; t++)
#pragma unroll
        for (int q = 0; q < 4; q++) av[t][q] = 0.f;

#pragma unroll
    for (int q = 0; q < 3; q++) {                 // 0: Phi*Vlo', 1: Plo'*Vhi, 2: Phi*Vhi
        uint32_t bB = (q == 0) ? uVlo : uVhi;
#pragma unroll
        for (int ks = 0; ks < 8; ks++) {
            float e00 = __uint_as_float(k0[4 * ks]);
            float e01 = __uint_as_float(k0[4 * ks + 1]);
            float e02 = __uint_as_float(k0[4 * ks + 2]);
            float e03 = __uint_as_float(k0[4 * ks + 3]);
            float e10 = __uint_as_float(k1[4 * ks]);
            float e11 = __uint_as_float(k1[4 * ks + 1]);
            float e12 = __uint_as_float(k1[4 * ks + 2]);
            float e13 = __uint_as_float(k1[4 * ks + 3]);
            uint32_t a[4];
            if (q == 1) {   // Plo' = (e - fp16(e)) * 2048
                a[0] = h2pack((e00 - __half2float(__float2half(e00))) * LOSCALE,
                              (e01 - __half2float(__float2half(e01))) * LOSCALE);
                a[1] = h2pack((e10 - __half2float(__float2half(e10))) * LOSCALE,
                              (e11 - __half2float(__float2half(e11))) * LOSCALE);
                a[2] = h2pack((e02 - __half2float(__float2half(e02))) * LOSCALE,
                              (e03 - __half2float(__float2half(e03))) * LOSCALE);
                a[3] = h2pack((e12 - __half2float(__float2half(e12))) * LOSCALE,
                              (e13 - __half2float(__float2half(e13))) * LOSCALE);
            } else {        // Phi
                a[0] = h2pack(e00, e01);
                a[1] = h2pack(e10, e11);
                a[2] = h2pack(e02, e03);
                a[3] = h2pack(e12, e13);
            }
            uint32_t colb = (uint32_t)(ks * 16 + (lane >> 4) * 8) * 2;
#pragma unroll
            for (int g = 0; g < 4; g++) {
                uint32_t bfr[4];
                ldm_x4(bfr, bB + (uint32_t)(g * 16 + (lane & 15)) * AVT * 2 + colb);
                mma16816(av[2 * g],     a, bfr[0], bfr[2]);
                mma16816(av[2 * g + 1], a, bfr[1], bfr[3]);
            }
        }
        if (q == 1) {
#pragma unroll
            for (int t = 0; t < 8; t++)
#pragma unroll
                for (int c = 0; c < 4; c++) av[t][c] *= INVLOSCALE;
        }
    }

    // ---- epilogue: normalize, split hi/lo, store ----
#pragma unroll
    for (int nt = 0; nt < 8; nt++) {
        int dn = nt * 8 + 2 * (lane & 3);
        size_t o0 = ((size_t)b * FDIM + r0) * DDIM + h * HD + dn;
        size_t o1 = ((size_t)b * FDIM + r1) * DDIM + h * HD + dn;
        uint32_t hi, lo;
        split2(av[nt][0] * inv0, av[nt][1] * inv0, hi, lo);
        *(uint32_t*)(g_ahi + o0) = hi;
        *(uint32_t*)(g_alo + o0) = lo;
        split2(av[nt][2] * inv1, av[nt][3] * inv1, hi, lo);
        *(uint32_t*)(g_ahi + o1) = hi;
        *(uint32_t*)(g_alo + o1) = lo;
    }
}

// ---------------- launch ----------------
extern "C" void kernel_launch(void* const* d_in, const int* in_sizes, int n_in,
                              void* d_out, int out_size)
{
    const float* x    = (const float*)d_in[0];
    const float* Wq   = (const float*)d_in[1];
    const float* bq   = (const float*)d_in[2];
    const float* Wk   = (const float*)d_in[3];
    const float* bk   = (const float*)d_in[4];
    const float* Wv   = (const float*)d_in[5];
    const float* bv   = (const float*)d_in[6];
    const float* Wo   = (const float*)d_in[7];
    const float* bo   = (const float*)d_in[8];
    const float* corr = (const float*)d_in[9];
    const float* fimp = (const float*)d_in[10];
    const float* W1   = (const float*)d_in[11];
    const float* b1   = (const float*)d_in[12];
    const float* W2   = (const float*)d_in[13];
    const float* b2   = (const float*)d_in[14];
    float* out = (float*)d_out;

    cudaFuncSetAttribute(gemm_mma, cudaFuncAttributeMaxDynamicSharedMemorySize, GEMM_SMEM);
    cudaFuncSetAttribute(attn_kernel, cudaFuncAttributeMaxDynamicSharedMemorySize, ATTN_SMEM);

    // prep: fp16 hi/lo splits of x and transposed weights
    split_kernel<<<16384, 256>>>((const float4*)x);
    wsplit_kernel<<<dim3(16, 16, 4), dim3(32, 32)>>>(Wq, Wk, Wv, Wo);
    pv_kernel<<<BSZ, 256>>>(x, W1, b1, W2, b2);

    // q,k,v projections on tensor cores (HMMA, 3-term split, K64 chunks)
    gemm_mma<<<dim3(4, 256, 3), 256, GEMM_SMEM>>>(0, bq, bk, bv, nullptr);

    // fused sparse attention on tensor cores (writes hi/lo split output directly)
    attn_kernel<<<BSZ * HH, 256, ATTN_SMEM>>>(corr, fimp);

    // output projection on tensor cores
    gemm_mma<<<dim3(4, 256, 1), 256, GEMM_SMEM>>>(1, bo, bo, bo, out);
}